// round 1
// baseline (speedup 1.0000x reference)
#include <cuda_runtime.h>
#include <cuda_bf16.h>
#include <math.h>

// Problem constants (fixed by the dataset)
#define N_NODES 100000
#define N_EDGES 1600000
#define D 64
#define EPSV 1e-7f

// Scratch (device globals -- allocation inside kernel_launch is forbidden)
__device__ float g_s1[N_NODES * D];   // sum of x[src]
__device__ float g_s2[N_NODES * D];   // sum of x[src]^2
__device__ int   g_deg[N_NODES];      // in-degree per dst

// ---------------------------------------------------------------------------
// Kernel 1: zero scratch
// ---------------------------------------------------------------------------
__global__ void zero_kernel() {
    const int n4 = N_NODES * D / 4;   // float4 count per array
    float4 z = make_float4(0.f, 0.f, 0.f, 0.f);
    float4* a = reinterpret_cast<float4*>(g_s1);
    float4* b = reinterpret_cast<float4*>(g_s2);
    for (int i = blockIdx.x * blockDim.x + threadIdx.x; i < n4;
         i += gridDim.x * blockDim.x) {
        a[i] = z;
        b[i] = z;
    }
    for (int i = blockIdx.x * blockDim.x + threadIdx.x; i < N_NODES;
         i += gridDim.x * blockDim.x) {
        g_deg[i] = 0;
    }
}

// ---------------------------------------------------------------------------
// Kernel 2: edge scatter. 16 lanes per edge, each lane handles 4 dims via
// vector reductions (red.global.add.v4.f32, sm_90+).
// ---------------------------------------------------------------------------
__device__ __forceinline__ void red_add_v4(float* addr, float4 v) {
    asm volatile("red.global.add.v4.f32 [%0], {%1, %2, %3, %4};"
                 :: "l"(addr), "f"(v.x), "f"(v.y), "f"(v.z), "f"(v.w)
                 : "memory");
}

__global__ void edge_kernel(const float* __restrict__ x,
                            const int* __restrict__ erow,   // dst
                            const int* __restrict__ ecol,   // src
                            int E) {
    int gid = blockIdx.x * blockDim.x + threadIdx.x;
    int e = gid >> 4;
    if (e >= E) return;
    int lane = gid & 15;

    int dst = erow[e];
    int src = ecol[e];

    float4 v = *reinterpret_cast<const float4*>(x + (size_t)src * D + lane * 4);
    float4 vv = make_float4(v.x * v.x, v.y * v.y, v.z * v.z, v.w * v.w);

    red_add_v4(g_s1 + (size_t)dst * D + lane * 4, v);
    red_add_v4(g_s2 + (size_t)dst * D + lane * 4, vv);

    if (lane == 0) atomicAdd(&g_deg[dst], 1);
}

// ---------------------------------------------------------------------------
// Kernel 3: fused finalize.
// out[n,o] = sum_{a,s} factor[s,n] * <agg[a,n,:], pre_w[a,s,o,:]>
//          + <x[n,:], lin_w[o,:]> + bias[o]
// Folding factors into the features gives one K=448 dot per (n,o):
//   Y[n] = [mean, f1*mean, f2*mean, std, f1*std, f2*std, x]  (448 floats)
//   Wcat = [pre_w[0..5] | lin_w]  each 64x64 row-major (out-major)
// CTA tiles 32 nodes; Y staged in smem; weights hit L1 (114 KB, resident).
// Thread tile: 2 nodes x 4 outputs.
// ---------------------------------------------------------------------------
__global__ void finalize_kernel(const float* __restrict__ x,
                                const float* __restrict__ pre_w,
                                const float* __restrict__ lin_w,
                                const float* __restrict__ bias,
                                const float* __restrict__ avg_ptr,
                                float* __restrict__ out,
                                int N) {
    extern __shared__ float Ysh[];                 // [32][448]
    const int tid = threadIdx.x;                   // 256 threads
    const int node0 = blockIdx.x * 32;
    const float avg = __ldg(avg_ptr);

    // ---- Stage augmented features for 32 nodes (2048 (n,i) pairs) ----
    #pragma unroll
    for (int t = 0; t < 8; ++t) {
        int p = tid + t * 256;                     // 0..2047
        int nl = p >> 6;                           // local node 0..31
        int i  = p & 63;                           // feature dim
        int n  = node0 + nl;
        float mean = 0.f, stdv = 0.f, xv = 0.f, f1 = 0.f, f2 = 0.f;
        if (n < N) {
            mean = g_s1[(size_t)n * D + i];
            float s2v = g_s2[(size_t)n * D + i];
            stdv = sqrtf(fmaxf(s2v - mean * mean, 0.f) + EPSV);
            xv = __ldg(x + (size_t)n * D + i);
            float degf = (float)g_deg[n];
            float logd = logf(degf + 1.0f);
            f1 = logd / avg;
            f2 = avg / (logd + EPSV);
        }
        float* Yr = Ysh + nl * 448;
        Yr[i]        = mean;
        Yr[64 + i]   = f1 * mean;
        Yr[128 + i]  = f2 * mean;
        Yr[192 + i]  = stdv;
        Yr[256 + i]  = f1 * stdv;
        Yr[320 + i]  = f2 * stdv;
        Yr[384 + i]  = xv;
    }
    __syncthreads();

    // ---- Register-tiled GEMM: K = 7*64 = 448 ----
    const int on = tid & 15;          // output group: outputs o0..o0+3
    const int ng = tid >> 4;          // node group: 2 nodes
    const int o0 = on * 4;
    const int na = ng * 2;

    const float* Ya = Ysh + na * 448;
    const float* Yb = Ya + 448;

    float acc[2][4];
    #pragma unroll
    for (int j = 0; j < 4; ++j) { acc[0][j] = 0.f; acc[1][j] = 0.f; }

    for (int seg = 0; seg < 7; ++seg) {
        const float* W = (seg < 6) ? (pre_w + seg * 4096) : lin_w;
        const float4* W0 = reinterpret_cast<const float4*>(W + (o0 + 0) * 64);
        const float4* W1 = reinterpret_cast<const float4*>(W + (o0 + 1) * 64);
        const float4* W2 = reinterpret_cast<const float4*>(W + (o0 + 2) * 64);
        const float4* W3 = reinterpret_cast<const float4*>(W + (o0 + 3) * 64);
        const float4* Fa = reinterpret_cast<const float4*>(Ya + seg * 64);
        const float4* Fb = reinterpret_cast<const float4*>(Yb + seg * 64);
        #pragma unroll
        for (int i4 = 0; i4 < 16; ++i4) {
            float4 ya = Fa[i4];
            float4 yb = Fb[i4];
            float4 w0 = __ldg(W0 + i4);
            float4 w1 = __ldg(W1 + i4);
            float4 w2 = __ldg(W2 + i4);
            float4 w3 = __ldg(W3 + i4);
            acc[0][0] += ya.x * w0.x + ya.y * w0.y + ya.z * w0.z + ya.w * w0.w;
            acc[0][1] += ya.x * w1.x + ya.y * w1.y + ya.z * w1.z + ya.w * w1.w;
            acc[0][2] += ya.x * w2.x + ya.y * w2.y + ya.z * w2.z + ya.w * w2.w;
            acc[0][3] += ya.x * w3.x + ya.y * w3.y + ya.z * w3.z + ya.w * w3.w;
            acc[1][0] += yb.x * w0.x + yb.y * w0.y + yb.z * w0.z + yb.w * w0.w;
            acc[1][1] += yb.x * w1.x + yb.y * w1.y + yb.z * w1.z + yb.w * w1.w;
            acc[1][2] += yb.x * w2.x + yb.y * w2.y + yb.z * w2.z + yb.w * w2.w;
            acc[1][3] += yb.x * w3.x + yb.y * w3.y + yb.z * w3.z + yb.w * w3.w;
        }
    }

    // ---- Epilogue: add bias, write ----
    float bz[4];
    #pragma unroll
    for (int j = 0; j < 4; ++j) bz[j] = __ldg(bias + o0 + j);

    int gna = node0 + na;
    if (gna < N) {
        #pragma unroll
        for (int j = 0; j < 4; ++j)
            out[(size_t)gna * D + o0 + j] = acc[0][j] + bz[j];
    }
    int gnb = gna + 1;
    if (gnb < N) {
        #pragma unroll
        for (int j = 0; j < 4; ++j)
            out[(size_t)gnb * D + o0 + j] = acc[1][j] + bz[j];
    }
}

// ---------------------------------------------------------------------------
// Launch
// Inputs (metadata order): x, edge_row, edge_col, pre_w, lin_w, bias,
//                          avg_deg_log
// ---------------------------------------------------------------------------
extern "C" void kernel_launch(void* const* d_in, const int* in_sizes, int n_in,
                              void* d_out, int out_size) {
    const float* x       = (const float*)d_in[0];
    const int*   erow    = (const int*)d_in[1];
    const int*   ecol    = (const int*)d_in[2];
    const float* pre_w   = (const float*)d_in[3];
    const float* lin_w   = (const float*)d_in[4];
    const float* bias    = (const float*)d_in[5];
    const float* avg_log = (const float*)d_in[6];

    const int N = in_sizes[0] / D;
    const int E = in_sizes[1];
    float* out = (float*)d_out;

    // 1) zero scratch
    zero_kernel<<<2048, 256>>>();

    // 2) edge scatter: 16 lanes per edge
    {
        long long threads = (long long)E * 16;
        int blocks = (int)((threads + 255) / 256);
        edge_kernel<<<blocks, 256>>>(x, erow, ecol, E);
    }

    // 3) fused finalize
    {
        static bool attr_set = false;
        if (!attr_set) {
            cudaFuncSetAttribute(finalize_kernel,
                                 cudaFuncAttributeMaxDynamicSharedMemorySize,
                                 32 * 448 * 4);
            attr_set = true;
        }
        int blocks = (N + 31) / 32;
        finalize_kernel<<<blocks, 256, 32 * 448 * 4>>>(
            x, pre_w, lin_w, bias, avg_log, out, N);
    }
}

// round 2
// speedup vs baseline: 1.0523x; 1.0523x over previous
#include <cuda_runtime.h>
#include <cuda_bf16.h>
#include <math.h>

#define N_NODES 100000
#define N_EDGES 1600000
#define D 64
#define EPSV 1e-7f
#define SCAN_BLK 1024
#define N_SCAN_BLKS ((N_NODES + SCAN_BLK - 1) / SCAN_BLK)   // 98

// Scratch (device globals; allocation is forbidden)
__device__ float g_s1[N_NODES * D];
__device__ float g_s2[N_NODES * D];
__device__ int   g_cnt[N_NODES];
__device__ int   g_rowptr[N_NODES + 1];
__device__ int   g_cur[N_NODES];
__device__ int   g_bsum[N_SCAN_BLKS];
__device__ int   g_csr[N_EDGES];

// ---------------------------------------------------------------------------
// K1: zero per-node counters
// ---------------------------------------------------------------------------
__global__ void zero_cnt_kernel(int n) {
    int i = blockIdx.x * blockDim.x + threadIdx.x;
    if (i < n) g_cnt[i] = 0;
}

// ---------------------------------------------------------------------------
// K2: histogram of destination degrees
// ---------------------------------------------------------------------------
__global__ void count_kernel(const int* __restrict__ erow, int E) {
    int e = blockIdx.x * blockDim.x + threadIdx.x;
    if (e < E) atomicAdd(&g_cnt[erow[e]], 1);
}

// ---------------------------------------------------------------------------
// K3a: per-block exclusive scan of g_cnt -> g_rowptr, block totals -> g_bsum
// ---------------------------------------------------------------------------
__global__ void scan_block_kernel(int n) {
    __shared__ int warp_sums[32];
    int i = blockIdx.x * SCAN_BLK + threadIdx.x;
    int v = (i < n) ? g_cnt[i] : 0;
    int lane = threadIdx.x & 31;
    int wid = threadIdx.x >> 5;

    int s = v;
    #pragma unroll
    for (int o = 1; o < 32; o <<= 1) {
        int t = __shfl_up_sync(0xffffffffu, s, o);
        if (lane >= o) s += t;
    }
    if (lane == 31) warp_sums[wid] = s;
    __syncthreads();
    if (wid == 0) {
        int ws = warp_sums[lane];
        #pragma unroll
        for (int o = 1; o < 32; o <<= 1) {
            int t = __shfl_up_sync(0xffffffffu, ws, o);
            if (lane >= o) ws += t;
        }
        warp_sums[lane] = ws;
    }
    __syncthreads();
    int warp_off = (wid == 0) ? 0 : warp_sums[wid - 1];
    if (i < n) g_rowptr[i] = warp_off + s - v;
    if (threadIdx.x == 0) g_bsum[blockIdx.x] = warp_sums[31];
}

// ---------------------------------------------------------------------------
// K3b: serial exclusive scan of block sums (98 elems, trivial)
// ---------------------------------------------------------------------------
__global__ void scan_top_kernel(int nb) {
    if (threadIdx.x == 0 && blockIdx.x == 0) {
        int acc = 0;
        for (int i = 0; i < nb; ++i) {
            int t = g_bsum[i];
            g_bsum[i] = acc;
            acc += t;
        }
    }
}

// ---------------------------------------------------------------------------
// K3c: add block offsets; init cursors; rowptr[n] = E
// ---------------------------------------------------------------------------
__global__ void scan_add_kernel(int n, int E) {
    int i = blockIdx.x * blockDim.x + threadIdx.x;
    if (i < n) {
        int r = g_rowptr[i] + g_bsum[i >> 10];
        g_rowptr[i] = r;
        g_cur[i] = r;
    }
    if (i == n) g_rowptr[n] = E;
}

// ---------------------------------------------------------------------------
// K4: bucket-scatter edge sources into CSR
// ---------------------------------------------------------------------------
__global__ void scatter_kernel(const int* __restrict__ erow,
                               const int* __restrict__ ecol, int E) {
    int e = blockIdx.x * blockDim.x + threadIdx.x;
    if (e < E) {
        int d = erow[e];
        int pos = atomicAdd(&g_cur[d], 1);
        g_csr[pos] = ecol[e];
    }
}

// ---------------------------------------------------------------------------
// K5: gather-aggregate. 16 threads per node, 4 dims per thread.
// Registers accumulate s1/s2; plain coalesced stores (no atomics).
// ---------------------------------------------------------------------------
__global__ void aggregate_kernel(const float* __restrict__ x, int N) {
    int gid = blockIdx.x * blockDim.x + threadIdx.x;
    int n = gid >> 4;
    if (n >= N) return;
    int lane = gid & 15;

    int beg = g_rowptr[n];
    int end = g_rowptr[n + 1];

    float4 a = make_float4(0.f, 0.f, 0.f, 0.f);
    float4 b = make_float4(0.f, 0.f, 0.f, 0.f);
    const float4* x4 = reinterpret_cast<const float4*>(x);

    for (int j = beg; j < end; ++j) {
        int s = __ldg(&g_csr[j]);
        float4 v = __ldg(&x4[(size_t)s * 16 + lane]);
        a.x += v.x; a.y += v.y; a.z += v.z; a.w += v.w;
        b.x += v.x * v.x; b.y += v.y * v.y; b.z += v.z * v.z; b.w += v.w * v.w;
    }

    size_t off = (size_t)n * 16 + lane;
    reinterpret_cast<float4*>(g_s1)[off] = a;
    reinterpret_cast<float4*>(g_s2)[off] = b;
}

// ---------------------------------------------------------------------------
// K6: fused finalize GEMM (K = 7*64 = 448 per output element)
// ---------------------------------------------------------------------------
__global__ void finalize_kernel(const float* __restrict__ x,
                                const float* __restrict__ pre_w,
                                const float* __restrict__ lin_w,
                                const float* __restrict__ bias,
                                const float* __restrict__ avg_ptr,
                                float* __restrict__ out,
                                int N) {
    extern __shared__ float Ysh[];                 // [32][448]
    const int tid = threadIdx.x;                   // 256 threads
    const int node0 = blockIdx.x * 32;
    const float avg = __ldg(avg_ptr);

    #pragma unroll
    for (int t = 0; t < 8; ++t) {
        int p = tid + t * 256;
        int nl = p >> 6;
        int i = p & 63;
        int n = node0 + nl;
        float mean = 0.f, stdv = 0.f, xv = 0.f, f1 = 0.f, f2 = 0.f;
        if (n < N) {
            mean = g_s1[(size_t)n * D + i];
            float s2v = g_s2[(size_t)n * D + i];
            stdv = sqrtf(fmaxf(s2v - mean * mean, 0.f) + EPSV);
            xv = __ldg(x + (size_t)n * D + i);
            float degf = (float)(g_rowptr[n + 1] - g_rowptr[n]);
            float logd = logf(degf + 1.0f);
            f1 = logd / avg;
            f2 = avg / (logd + EPSV);
        }
        float* Yr = Ysh + nl * 448;
        Yr[i]       = mean;
        Yr[64 + i]  = f1 * mean;
        Yr[128 + i] = f2 * mean;
        Yr[192 + i] = stdv;
        Yr[256 + i] = f1 * stdv;
        Yr[320 + i] = f2 * stdv;
        Yr[384 + i] = xv;
    }
    __syncthreads();

    const int on = tid & 15;
    const int ng = tid >> 4;
    const int o0 = on * 4;
    const int na = ng * 2;

    const float* Ya = Ysh + na * 448;
    const float* Yb = Ya + 448;

    float acc[2][4];
    #pragma unroll
    for (int j = 0; j < 4; ++j) { acc[0][j] = 0.f; acc[1][j] = 0.f; }

    for (int seg = 0; seg < 7; ++seg) {
        const float* W = (seg < 6) ? (pre_w + seg * 4096) : lin_w;
        const float4* W0 = reinterpret_cast<const float4*>(W + (o0 + 0) * 64);
        const float4* W1 = reinterpret_cast<const float4*>(W + (o0 + 1) * 64);
        const float4* W2 = reinterpret_cast<const float4*>(W + (o0 + 2) * 64);
        const float4* W3 = reinterpret_cast<const float4*>(W + (o0 + 3) * 64);
        const float4* Fa = reinterpret_cast<const float4*>(Ya + seg * 64);
        const float4* Fb = reinterpret_cast<const float4*>(Yb + seg * 64);
        #pragma unroll
        for (int i4 = 0; i4 < 16; ++i4) {
            float4 ya = Fa[i4];
            float4 yb = Fb[i4];
            float4 w0 = __ldg(W0 + i4);
            float4 w1 = __ldg(W1 + i4);
            float4 w2 = __ldg(W2 + i4);
            float4 w3 = __ldg(W3 + i4);
            acc[0][0] += ya.x * w0.x + ya.y * w0.y + ya.z * w0.z + ya.w * w0.w;
            acc[0][1] += ya.x * w1.x + ya.y * w1.y + ya.z * w1.z + ya.w * w1.w;
            acc[0][2] += ya.x * w2.x + ya.y * w2.y + ya.z * w2.z + ya.w * w2.w;
            acc[0][3] += ya.x * w3.x + ya.y * w3.y + ya.z * w3.z + ya.w * w3.w;
            acc[1][0] += yb.x * w0.x + yb.y * w0.y + yb.z * w0.z + yb.w * w0.w;
            acc[1][1] += yb.x * w1.x + yb.y * w1.y + yb.z * w1.z + yb.w * w1.w;
            acc[1][2] += yb.x * w2.x + yb.y * w2.y + yb.z * w2.z + yb.w * w2.w;
            acc[1][3] += yb.x * w3.x + yb.y * w3.y + yb.z * w3.z + yb.w * w3.w;
        }
    }

    float bz[4];
    #pragma unroll
    for (int j = 0; j < 4; ++j) bz[j] = __ldg(bias + o0 + j);

    int gna = node0 + na;
    if (gna < N) {
        #pragma unroll
        for (int j = 0; j < 4; ++j)
            out[(size_t)gna * D + o0 + j] = acc[0][j] + bz[j];
    }
    int gnb = gna + 1;
    if (gnb < N) {
        #pragma unroll
        for (int j = 0; j < 4; ++j)
            out[(size_t)gnb * D + o0 + j] = acc[1][j] + bz[j];
    }
}

// ---------------------------------------------------------------------------
// Launch. Inputs: x, edge_row, edge_col, pre_w, lin_w, bias, avg_deg_log
// ---------------------------------------------------------------------------
extern "C" void kernel_launch(void* const* d_in, const int* in_sizes, int n_in,
                              void* d_out, int out_size) {
    const float* x       = (const float*)d_in[0];
    const int*   erow    = (const int*)d_in[1];
    const int*   ecol    = (const int*)d_in[2];
    const float* pre_w   = (const float*)d_in[3];
    const float* lin_w   = (const float*)d_in[4];
    const float* bias    = (const float*)d_in[5];
    const float* avg_log = (const float*)d_in[6];

    const int N = in_sizes[0] / D;
    const int E = in_sizes[1];
    float* out = (float*)d_out;

    // CSR build
    zero_cnt_kernel<<<(N + 255) / 256, 256>>>(N);
    count_kernel<<<(E + 255) / 256, 256>>>(erow, E);
    int nsb = (N + SCAN_BLK - 1) / SCAN_BLK;
    scan_block_kernel<<<nsb, SCAN_BLK>>>(N);
    scan_top_kernel<<<1, 32>>>(nsb);
    scan_add_kernel<<<(N + 256) / 256, 256>>>(N, E);
    scatter_kernel<<<(E + 255) / 256, 256>>>(erow, ecol, E);

    // Gather-aggregate (no atomics)
    {
        long long threads = (long long)N * 16;
        int blocks = (int)((threads + 255) / 256);
        aggregate_kernel<<<blocks, 256>>>(x, N);
    }

    // Fused finalize GEMM
    {
        cudaFuncSetAttribute(finalize_kernel,
                             cudaFuncAttributeMaxDynamicSharedMemorySize,
                             32 * 448 * 4);
        int blocks = (N + 31) / 32;
        finalize_kernel<<<blocks, 256, 32 * 448 * 4>>>(
            x, pre_w, lin_w, bias, avg_log, out, N);
    }
}

// round 4
// speedup vs baseline: 3.1143x; 2.9595x over previous
#include <cuda_runtime.h>
#include <cuda_bf16.h>
#include <math.h>

#define N_NODES 100000
#define N_EDGES 1600000
#define D 64
#define EPSV 1e-7f

// Scratch (device globals; allocation is forbidden)
__device__ float g_s1[N_NODES * D];
__device__ float g_s2[N_NODES * D];
__device__ int   g_cnt[N_NODES];
__device__ int   g_rowptr[N_NODES + 1];
__device__ int   g_cur[N_NODES];
__device__ int   g_csr[N_EDGES];
__device__ float g_wt[448 * 64];     // permuted weights (k-pair interleaved)

// ---------------------------------------------------------------------------
// K0: permute weights into lane-coalesced k-pair-interleaved layout.
// Logical W[k][o], k in [0,448), o in [0,64); k-seg order matches Y layout.
// Dest float index for (k, o):
//   kk = k>>1, klo = k&1, og = o>>2, r = o&3, half = r>>1, slot = r&1
//   didx = kk*128 + half*64 + og*4 + slot*2 + klo
// Finalize reads, per kk, lane og:
//   ulonglong2 at float offset kk*128 +      og*4  -> pairs (o0, o0+1)
//   ulonglong2 at float offset kk*128 + 64 + og*4  -> pairs (o0+2, o0+3)
// In ulonglong2 units (4 floats each): kk*32 + og and kk*32 + 16 + og.
// Lanes 0..15 cover 256 B contiguous per load.
// ---------------------------------------------------------------------------
__global__ void permute_w_kernel(const float* __restrict__ pre_w,
                                 const float* __restrict__ lin_w) {
    int idx = blockIdx.x * blockDim.x + threadIdx.x;   // 0..28671
    if (idx >= 448 * 64) return;
    int k = idx >> 6;
    int o = idx & 63;
    int seg = k >> 6;
    int ki = k & 63;
    const float* W = (seg < 6) ? (pre_w + seg * 4096) : lin_w;
    float v = W[o * 64 + ki];
    int kk = k >> 1, klo = k & 1;
    int og = o >> 2, r = o & 3;
    int didx = kk * 128 + (r >> 1) * 64 + og * 4 + (r & 1) * 2 + klo;
    g_wt[didx] = v;
}

// ---------------------------------------------------------------------------
// K1: zero per-node counters
// ---------------------------------------------------------------------------
__global__ void zero_cnt_kernel(int n) {
    int i = blockIdx.x * blockDim.x + threadIdx.x;
    if (i < n) g_cnt[i] = 0;
}

// ---------------------------------------------------------------------------
// K2: histogram of destination degrees
// ---------------------------------------------------------------------------
__global__ void count_kernel(const int* __restrict__ erow, int E) {
    int e = blockIdx.x * blockDim.x + threadIdx.x;
    if (e < E) atomicAdd(&g_cnt[erow[e]], 1);
}

// ---------------------------------------------------------------------------
// K3: single-block exclusive scan of g_cnt -> g_rowptr + g_cur, rowptr[N]=E.
// ---------------------------------------------------------------------------
__global__ void scan_kernel(int N, int E) {
    __shared__ int warp_sums[32];
    const int C = (N + 1023) / 1024;
    int t = threadIdx.x;
    int start = t * C;

    int sum = 0;
    for (int i = 0; i < C; ++i) {
        int idx = start + i;
        if (idx < N) sum += g_cnt[idx];
    }
    int lane = t & 31, wid = t >> 5;
    int s = sum;
    #pragma unroll
    for (int o = 1; o < 32; o <<= 1) {
        int v = __shfl_up_sync(0xffffffffu, s, o);
        if (lane >= o) s += v;
    }
    if (lane == 31) warp_sums[wid] = s;
    __syncthreads();
    if (wid == 0) {
        int ws = warp_sums[lane];
        #pragma unroll
        for (int o = 1; o < 32; o <<= 1) {
            int v = __shfl_up_sync(0xffffffffu, ws, o);
            if (lane >= o) ws += v;
        }
        warp_sums[lane] = ws;
    }
    __syncthreads();
    int excl = s - sum + ((wid == 0) ? 0 : warp_sums[wid - 1]);

    int run = excl;
    for (int i = 0; i < C; ++i) {
        int idx = start + i;
        if (idx < N) {
            g_rowptr[idx] = run;
            g_cur[idx] = run;
            run += g_cnt[idx];
        }
    }
    if (t == 0) g_rowptr[N] = E;
}

// ---------------------------------------------------------------------------
// K4: bucket-scatter edge sources into CSR
// ---------------------------------------------------------------------------
__global__ void scatter_kernel(const int* __restrict__ erow,
                               const int* __restrict__ ecol, int E) {
    int e = blockIdx.x * blockDim.x + threadIdx.x;
    if (e < E) {
        int d = erow[e];
        int pos = atomicAdd(&g_cur[d], 1);
        g_csr[pos] = ecol[e];
    }
}

// ---------------------------------------------------------------------------
// K5: gather-aggregate, 16 lanes/node, unrolled by 2 for MLP.
// ---------------------------------------------------------------------------
__global__ void aggregate_kernel(const float* __restrict__ x, int N) {
    int gid = blockIdx.x * blockDim.x + threadIdx.x;
    int n = gid >> 4;
    if (n >= N) return;
    int lane = gid & 15;

    int beg = g_rowptr[n];
    int end = g_rowptr[n + 1];

    float4 a = make_float4(0.f, 0.f, 0.f, 0.f);
    float4 b = make_float4(0.f, 0.f, 0.f, 0.f);
    const float4* x4 = reinterpret_cast<const float4*>(x);

    int j = beg;
    for (; j + 1 < end; j += 2) {
        int s0 = __ldg(&g_csr[j]);
        int s1 = __ldg(&g_csr[j + 1]);
        float4 v0 = __ldg(&x4[(size_t)s0 * 16 + lane]);
        float4 v1 = __ldg(&x4[(size_t)s1 * 16 + lane]);
        a.x += v0.x; a.y += v0.y; a.z += v0.z; a.w += v0.w;
        b.x += v0.x * v0.x; b.y += v0.y * v0.y;
        b.z += v0.z * v0.z; b.w += v0.w * v0.w;
        a.x += v1.x; a.y += v1.y; a.z += v1.z; a.w += v1.w;
        b.x += v1.x * v1.x; b.y += v1.y * v1.y;
        b.z += v1.z * v1.z; b.w += v1.w * v1.w;
    }
    if (j < end) {
        int s0 = __ldg(&g_csr[j]);
        float4 v0 = __ldg(&x4[(size_t)s0 * 16 + lane]);
        a.x += v0.x; a.y += v0.y; a.z += v0.z; a.w += v0.w;
        b.x += v0.x * v0.x; b.y += v0.y * v0.y;
        b.z += v0.z * v0.z; b.w += v0.w * v0.w;
    }

    size_t off = (size_t)n * 16 + lane;
    reinterpret_cast<float4*>(g_s1)[off] = a;
    reinterpret_cast<float4*>(g_s2)[off] = b;
}

// ---------------------------------------------------------------------------
// K6: finalize GEMM, FFMA2 (fma.rn.f32x2) packed along k.
// 64 nodes per CTA, 256 threads: og = tid&15 (4 outs), ng = tid>>4 (4 nodes).
// ---------------------------------------------------------------------------
__device__ __forceinline__ unsigned long long ffma2(
    unsigned long long a, unsigned long long b, unsigned long long c) {
    unsigned long long d;
    asm("fma.rn.f32x2 %0, %1, %2, %3;" : "=l"(d) : "l"(a), "l"(b), "l"(c));
    return d;
}

__global__ void __launch_bounds__(256, 1)
finalize_kernel(const float* __restrict__ x,
                const float* __restrict__ bias,
                const float* __restrict__ avg_ptr,
                float* __restrict__ out,
                int N) {
    extern __shared__ float Ysh[];                 // [64][448]
    __shared__ float f1s[64], f2s[64];
    const int tid = threadIdx.x;
    const int node0 = blockIdx.x * 64;

    if (tid < 64) {
        int n = node0 + tid;
        float f1 = 0.f, f2 = 0.f;
        if (n < N) {
            float avg = __ldg(avg_ptr);
            float degf = (float)(g_rowptr[n + 1] - g_rowptr[n]);
            float logd = logf(degf + 1.0f);
            f1 = logd / avg;
            f2 = avg / (logd + EPSV);
        }
        f1s[tid] = f1;
        f2s[tid] = f2;
    }
    __syncthreads();

    #pragma unroll
    for (int t = 0; t < 16; ++t) {
        int p = tid + t * 256;
        int nl = p >> 6;
        int i = p & 63;
        int n = node0 + nl;
        float mean = 0.f, stdv = 0.f, xv = 0.f;
        if (n < N) {
            mean = g_s1[(size_t)n * D + i];
            float s2v = g_s2[(size_t)n * D + i];
            stdv = sqrtf(fmaxf(s2v - mean * mean, 0.f) + EPSV);
            xv = __ldg(x + (size_t)n * D + i);
        }
        float f1 = f1s[nl], f2 = f2s[nl];
        float* Yr = Ysh + nl * 448;
        Yr[i]       = mean;
        Yr[64 + i]  = f1 * mean;
        Yr[128 + i] = f2 * mean;
        Yr[192 + i] = stdv;
        Yr[256 + i] = f1 * stdv;
        Yr[320 + i] = f2 * stdv;
        Yr[384 + i] = xv;
    }
    __syncthreads();

    const int og = tid & 15;          // outs o0..o0+3, o0 = og*4
    const int ng = tid >> 4;          // nodes na..na+3, na = ng*4
    const int o0 = og * 4;
    const int na = ng * 4;

    unsigned long long acc[4][4];
    #pragma unroll
    for (int j = 0; j < 4; ++j)
        #pragma unroll
        for (int q = 0; q < 4; ++q) acc[j][q] = 0ull;

    const ulonglong2* wbase = reinterpret_cast<const ulonglong2*>(g_wt);
    const unsigned long long* Y0 =
        reinterpret_cast<const unsigned long long*>(Ysh + na * 448);
    const unsigned long long* Y1 =
        reinterpret_cast<const unsigned long long*>(Ysh + (na + 1) * 448);
    const unsigned long long* Y2 =
        reinterpret_cast<const unsigned long long*>(Ysh + (na + 2) * 448);
    const unsigned long long* Y3 =
        reinterpret_cast<const unsigned long long*>(Ysh + (na + 3) * 448);

    #pragma unroll 4
    for (int kk = 0; kk < 224; ++kk) {
        // FIX (R3 bug): kk-block stride is 128 floats = 32 ulonglong2, not 16.
        ulonglong2 wlo = __ldg(wbase + kk * 32 + og);         // pairs o0, o0+1
        ulonglong2 whi = __ldg(wbase + kk * 32 + 16 + og);    // pairs o0+2, o0+3
        unsigned long long y0 = Y0[kk];
        unsigned long long y1 = Y1[kk];
        unsigned long long y2 = Y2[kk];
        unsigned long long y3 = Y3[kk];
        acc[0][0] = ffma2(y0, wlo.x, acc[0][0]);
        acc[0][1] = ffma2(y0, wlo.y, acc[0][1]);
        acc[0][2] = ffma2(y0, whi.x, acc[0][2]);
        acc[0][3] = ffma2(y0, whi.y, acc[0][3]);
        acc[1][0] = ffma2(y1, wlo.x, acc[1][0]);
        acc[1][1] = ffma2(y1, wlo.y, acc[1][1]);
        acc[1][2] = ffma2(y1, whi.x, acc[1][2]);
        acc[1][3] = ffma2(y1, whi.y, acc[1][3]);
        acc[2][0] = ffma2(y2, wlo.x, acc[2][0]);
        acc[2][1] = ffma2(y2, wlo.y, acc[2][1]);
        acc[2][2] = ffma2(y2, whi.x, acc[2][2]);
        acc[2][3] = ffma2(y2, whi.y, acc[2][3]);
        acc[3][0] = ffma2(y3, wlo.x, acc[3][0]);
        acc[3][1] = ffma2(y3, wlo.y, acc[3][1]);
        acc[3][2] = ffma2(y3, whi.x, acc[3][2]);
        acc[3][3] = ffma2(y3, whi.y, acc[3][3]);
    }

    float bz[4];
    #pragma unroll
    for (int q = 0; q < 4; ++q) bz[q] = __ldg(bias + o0 + q);

    #pragma unroll
    for (int j = 0; j < 4; ++j) {
        int n = node0 + na + j;
        if (n < N) {
            float4 r;
            float2 p0 = *reinterpret_cast<float2*>(&acc[j][0]);
            float2 p1 = *reinterpret_cast<float2*>(&acc[j][1]);
            float2 p2 = *reinterpret_cast<float2*>(&acc[j][2]);
            float2 p3 = *reinterpret_cast<float2*>(&acc[j][3]);
            r.x = p0.x + p0.y + bz[0];
            r.y = p1.x + p1.y + bz[1];
            r.z = p2.x + p2.y + bz[2];
            r.w = p3.x + p3.y + bz[3];
            *reinterpret_cast<float4*>(out + (size_t)n * D + o0) = r;
        }
    }
}

// ---------------------------------------------------------------------------
// Launch. Inputs: x, edge_row, edge_col, pre_w, lin_w, bias, avg_deg_log
// ---------------------------------------------------------------------------
extern "C" void kernel_launch(void* const* d_in, const int* in_sizes, int n_in,
                              void* d_out, int out_size) {
    const float* x       = (const float*)d_in[0];
    const int*   erow    = (const int*)d_in[1];
    const int*   ecol    = (const int*)d_in[2];
    const float* pre_w   = (const float*)d_in[3];
    const float* lin_w   = (const float*)d_in[4];
    const float* bias    = (const float*)d_in[5];
    const float* avg_log = (const float*)d_in[6];

    const int N = in_sizes[0] / D;
    const int E = in_sizes[1];
    float* out = (float*)d_out;

    permute_w_kernel<<<112, 256>>>(pre_w, lin_w);
    zero_cnt_kernel<<<(N + 255) / 256, 256>>>(N);
    count_kernel<<<(E + 255) / 256, 256>>>(erow, E);
    scan_kernel<<<1, 1024>>>(N, E);
    scatter_kernel<<<(E + 255) / 256, 256>>>(erow, ecol, E);

    {
        long long threads = (long long)N * 16;
        int blocks = (int)((threads + 255) / 256);
        aggregate_kernel<<<blocks, 256>>>(x, N);
    }

    {
        cudaFuncSetAttribute(finalize_kernel,
                             cudaFuncAttributeMaxDynamicSharedMemorySize,
                             64 * 448 * 4);
        int blocks = (N + 63) / 64;
        finalize_kernel<<<blocks, 256, 64 * 448 * 4>>>(
            x, bias, avg_log, out, N);
    }
}

// round 5
// speedup vs baseline: 4.5049x; 1.4465x over previous
#include <cuda_runtime.h>
#include <cuda_bf16.h>
#include <math.h>

#define N_NODES 100000
#define N_EDGES 1600000
#define D 64
#define EPSV 1e-7f
#define SCAN_BLK 1024
#define N_SCAN_BLKS ((N_NODES + SCAN_BLK - 1) / SCAN_BLK)   // 98

// Scratch (device globals; allocation is forbidden)
__device__ float g_s1[N_NODES * D];
__device__ float g_s2[N_NODES * D];
__device__ int   g_cnt[N_NODES];
__device__ int   g_rowptr[N_NODES + 1];
__device__ int   g_cur[N_NODES];
__device__ int   g_bsum[N_SCAN_BLKS];
__device__ int   g_csr[N_EDGES];
__device__ float g_wt[448 * 64];     // permuted weights (k-pair interleaved)

// ---------------------------------------------------------------------------
// K0: permute weights into lane-coalesced k-pair-interleaved layout.
//   kk = k>>1, klo = k&1, og = o>>2, r = o&3
//   didx = kk*128 + (r>>1)*64 + og*4 + (r&1)*2 + klo
// ---------------------------------------------------------------------------
__global__ void permute_w_kernel(const float* __restrict__ pre_w,
                                 const float* __restrict__ lin_w) {
    int idx = blockIdx.x * blockDim.x + threadIdx.x;   // 0..28671
    if (idx >= 448 * 64) return;
    int k = idx >> 6;
    int o = idx & 63;
    int seg = k >> 6;
    int ki = k & 63;
    const float* W = (seg < 6) ? (pre_w + seg * 4096) : lin_w;
    float v = W[o * 64 + ki];
    int kk = k >> 1, klo = k & 1;
    int og = o >> 2, r = o & 3;
    int didx = kk * 128 + (r >> 1) * 64 + og * 4 + (r & 1) * 2 + klo;
    g_wt[didx] = v;
}

// ---------------------------------------------------------------------------
// K1: zero per-node counters
// ---------------------------------------------------------------------------
__global__ void zero_cnt_kernel(int n) {
    int i = blockIdx.x * blockDim.x + threadIdx.x;
    if (i < n) g_cnt[i] = 0;
}

// ---------------------------------------------------------------------------
// K2: histogram of destination degrees
// ---------------------------------------------------------------------------
__global__ void count_kernel(const int* __restrict__ erow, int E) {
    int e = blockIdx.x * blockDim.x + threadIdx.x;
    if (e < E) atomicAdd(&g_cnt[erow[e]], 1);
}

// ---------------------------------------------------------------------------
// K3a: per-block exclusive scan of g_cnt -> g_rowptr; block totals -> g_bsum
// ---------------------------------------------------------------------------
__global__ void scan_block_kernel(int n) {
    __shared__ int warp_sums[32];
    int i = blockIdx.x * SCAN_BLK + threadIdx.x;
    int v = (i < n) ? g_cnt[i] : 0;
    int lane = threadIdx.x & 31;
    int wid = threadIdx.x >> 5;

    int s = v;
    #pragma unroll
    for (int o = 1; o < 32; o <<= 1) {
        int t = __shfl_up_sync(0xffffffffu, s, o);
        if (lane >= o) s += t;
    }
    if (lane == 31) warp_sums[wid] = s;
    __syncthreads();
    if (wid == 0) {
        int ws = warp_sums[lane];
        #pragma unroll
        for (int o = 1; o < 32; o <<= 1) {
            int t = __shfl_up_sync(0xffffffffu, ws, o);
            if (lane >= o) ws += t;
        }
        warp_sums[lane] = ws;
    }
    __syncthreads();
    int warp_off = (wid == 0) ? 0 : warp_sums[wid - 1];
    if (i < n) g_rowptr[i] = warp_off + s - v;
    if (threadIdx.x == SCAN_BLK - 1) g_bsum[blockIdx.x] = warp_off + s;
}

// ---------------------------------------------------------------------------
// K3b: parallel exclusive scan of the 98 block sums (1 block, 128 threads)
// ---------------------------------------------------------------------------
__global__ void scan_top_kernel(int nb) {
    __shared__ int sh[128];
    int t = threadIdx.x;
    int v = (t < nb) ? g_bsum[t] : 0;
    int lane = t & 31, wid = t >> 5;
    int s = v;
    #pragma unroll
    for (int o = 1; o < 32; o <<= 1) {
        int u = __shfl_up_sync(0xffffffffu, s, o);
        if (lane >= o) s += u;
    }
    if (lane == 31) sh[wid] = s;
    __syncthreads();
    if (t == 0) {
        int acc = 0;
        #pragma unroll
        for (int w = 0; w < 4; ++w) { int x = sh[w]; sh[w] = acc; acc += x; }
    }
    __syncthreads();
    if (t < nb) g_bsum[t] = sh[wid] + s - v;
}

// ---------------------------------------------------------------------------
// K3c: add block offsets; init cursors; rowptr[N] = E
// ---------------------------------------------------------------------------
__global__ void scan_add_kernel(int n, int E) {
    int i = blockIdx.x * blockDim.x + threadIdx.x;
    if (i < n) {
        int r = g_rowptr[i] + g_bsum[i >> 10];
        g_rowptr[i] = r;
        g_cur[i] = r;
    }
    if (i == n) g_rowptr[n] = E;
}

// ---------------------------------------------------------------------------
// K4: bucket-scatter edge sources into CSR
// ---------------------------------------------------------------------------
__global__ void scatter_kernel(const int* __restrict__ erow,
                               const int* __restrict__ ecol, int E) {
    int e = blockIdx.x * blockDim.x + threadIdx.x;
    if (e < E) {
        int d = erow[e];
        int pos = atomicAdd(&g_cur[d], 1);
        g_csr[pos] = ecol[e];
    }
}

// ---------------------------------------------------------------------------
// K5: gather-aggregate, 16 lanes/node, unrolled by 2 for MLP.
// ---------------------------------------------------------------------------
__global__ void aggregate_kernel(const float* __restrict__ x, int N) {
    int gid = blockIdx.x * blockDim.x + threadIdx.x;
    int n = gid >> 4;
    if (n >= N) return;
    int lane = gid & 15;

    int beg = g_rowptr[n];
    int end = g_rowptr[n + 1];

    float4 a = make_float4(0.f, 0.f, 0.f, 0.f);
    float4 b = make_float4(0.f, 0.f, 0.f, 0.f);
    const float4* x4 = reinterpret_cast<const float4*>(x);

    int j = beg;
    for (; j + 1 < end; j += 2) {
        int s0 = __ldg(&g_csr[j]);
        int s1 = __ldg(&g_csr[j + 1]);
        float4 v0 = __ldg(&x4[(size_t)s0 * 16 + lane]);
        float4 v1 = __ldg(&x4[(size_t)s1 * 16 + lane]);
        a.x += v0.x; a.y += v0.y; a.z += v0.z; a.w += v0.w;
        b.x += v0.x * v0.x; b.y += v0.y * v0.y;
        b.z += v0.z * v0.z; b.w += v0.w * v0.w;
        a.x += v1.x; a.y += v1.y; a.z += v1.z; a.w += v1.w;
        b.x += v1.x * v1.x; b.y += v1.y * v1.y;
        b.z += v1.z * v1.z; b.w += v1.w * v1.w;
    }
    if (j < end) {
        int s0 = __ldg(&g_csr[j]);
        float4 v0 = __ldg(&x4[(size_t)s0 * 16 + lane]);
        a.x += v0.x; a.y += v0.y; a.z += v0.z; a.w += v0.w;
        b.x += v0.x * v0.x; b.y += v0.y * v0.y;
        b.z += v0.z * v0.z; b.w += v0.w * v0.w;
    }

    size_t off = (size_t)n * 16 + lane;
    reinterpret_cast<float4*>(g_s1)[off] = a;
    reinterpret_cast<float4*>(g_s2)[off] = b;
}

// ---------------------------------------------------------------------------
// K6: finalize GEMM, FFMA2 (fma.rn.f32x2) packed along k.
// 64 nodes/CTA, 256 threads: og = tid&15 (4 outs), ng = tid>>4 (4 nodes).
// ---------------------------------------------------------------------------
__device__ __forceinline__ unsigned long long ffma2(
    unsigned long long a, unsigned long long b, unsigned long long c) {
    unsigned long long d;
    asm("fma.rn.f32x2 %0, %1, %2, %3;" : "=l"(d) : "l"(a), "l"(b), "l"(c));
    return d;
}

__global__ void __launch_bounds__(256, 1)
finalize_kernel(const float* __restrict__ x,
                const float* __restrict__ bias,
                const float* __restrict__ avg_ptr,
                float* __restrict__ out,
                int N) {
    extern __shared__ float Ysh[];                 // [64][448]
    __shared__ float f1s[64], f2s[64];
    const int tid = threadIdx.x;
    const int node0 = blockIdx.x * 64;

    if (tid < 64) {
        int n = node0 + tid;
        float f1 = 0.f, f2 = 0.f;
        if (n < N) {
            float avg = __ldg(avg_ptr);
            float degf = (float)(g_rowptr[n + 1] - g_rowptr[n]);
            float logd = logf(degf + 1.0f);
            f1 = logd / avg;
            f2 = avg / (logd + EPSV);
        }
        f1s[tid] = f1;
        f2s[tid] = f2;
    }
    __syncthreads();

    #pragma unroll
    for (int t = 0; t < 16; ++t) {
        int p = tid + t * 256;
        int nl = p >> 6;
        int i = p & 63;
        int n = node0 + nl;
        float mean = 0.f, stdv = 0.f, xv = 0.f;
        if (n < N) {
            mean = g_s1[(size_t)n * D + i];
            float s2v = g_s2[(size_t)n * D + i];
            stdv = sqrtf(fmaxf(s2v - mean * mean, 0.f) + EPSV);
            xv = __ldg(x + (size_t)n * D + i);
        }
        float f1 = f1s[nl], f2 = f2s[nl];
        float* Yr = Ysh + nl * 448;
        Yr[i]       = mean;
        Yr[64 + i]  = f1 * mean;
        Yr[128 + i] = f2 * mean;
        Yr[192 + i] = stdv;
        Yr[256 + i] = f1 * stdv;
        Yr[320 + i] = f2 * stdv;
        Yr[384 + i] = xv;
    }
    __syncthreads();

    const int og = tid & 15;
    const int ng = tid >> 4;
    const int o0 = og * 4;
    const int na = ng * 4;

    unsigned long long acc[4][4];
    #pragma unroll
    for (int j = 0; j < 4; ++j)
        #pragma unroll
        for (int q = 0; q < 4; ++q) acc[j][q] = 0ull;

    const ulonglong2* wbase = reinterpret_cast<const ulonglong2*>(g_wt);
    const unsigned long long* Y0 =
        reinterpret_cast<const unsigned long long*>(Ysh + na * 448);
    const unsigned long long* Y1 =
        reinterpret_cast<const unsigned long long*>(Ysh + (na + 1) * 448);
    const unsigned long long* Y2 =
        reinterpret_cast<const unsigned long long*>(Ysh + (na + 2) * 448);
    const unsigned long long* Y3 =
        reinterpret_cast<const unsigned long long*>(Ysh + (na + 3) * 448);

    #pragma unroll 4
    for (int kk = 0; kk < 224; ++kk) {
        ulonglong2 wlo = __ldg(wbase + kk * 32 + og);         // pairs o0, o0+1
        ulonglong2 whi = __ldg(wbase + kk * 32 + 16 + og);    // pairs o0+2, o0+3
        unsigned long long y0 = Y0[kk];
        unsigned long long y1 = Y1[kk];
        unsigned long long y2 = Y2[kk];
        unsigned long long y3 = Y3[kk];
        acc[0][0] = ffma2(y0, wlo.x, acc[0][0]);
        acc[0][1] = ffma2(y0, wlo.y, acc[0][1]);
        acc[0][2] = ffma2(y0, whi.x, acc[0][2]);
        acc[0][3] = ffma2(y0, whi.y, acc[0][3]);
        acc[1][0] = ffma2(y1, wlo.x, acc[1][0]);
        acc[1][1] = ffma2(y1, wlo.y, acc[1][1]);
        acc[1][2] = ffma2(y1, whi.x, acc[1][2]);
        acc[1][3] = ffma2(y1, whi.y, acc[1][3]);
        acc[2][0] = ffma2(y2, wlo.x, acc[2][0]);
        acc[2][1] = ffma2(y2, wlo.y, acc[2][1]);
        acc[2][2] = ffma2(y2, whi.x, acc[2][2]);
        acc[2][3] = ffma2(y2, whi.y, acc[2][3]);
        acc[3][0] = ffma2(y3, wlo.x, acc[3][0]);
        acc[3][1] = ffma2(y3, wlo.y, acc[3][1]);
        acc[3][2] = ffma2(y3, whi.x, acc[3][2]);
        acc[3][3] = ffma2(y3, whi.y, acc[3][3]);
    }

    float bz[4];
    #pragma unroll
    for (int q = 0; q < 4; ++q) bz[q] = __ldg(bias + o0 + q);

    #pragma unroll
    for (int j = 0; j < 4; ++j) {
        int n = node0 + na + j;
        if (n < N) {
            float4 r;
            float2 p0 = *reinterpret_cast<float2*>(&acc[j][0]);
            float2 p1 = *reinterpret_cast<float2*>(&acc[j][1]);
            float2 p2 = *reinterpret_cast<float2*>(&acc[j][2]);
            float2 p3 = *reinterpret_cast<float2*>(&acc[j][3]);
            r.x = p0.x + p0.y + bz[0];
            r.y = p1.x + p1.y + bz[1];
            r.z = p2.x + p2.y + bz[2];
            r.w = p3.x + p3.y + bz[3];
            *reinterpret_cast<float4*>(out + (size_t)n * D + o0) = r;
        }
    }
}

// ---------------------------------------------------------------------------
// Launch. Inputs: x, edge_row, edge_col, pre_w, lin_w, bias, avg_deg_log
// ---------------------------------------------------------------------------
extern "C" void kernel_launch(void* const* d_in, const int* in_sizes, int n_in,
                              void* d_out, int out_size) {
    const float* x       = (const float*)d_in[0];
    const int*   erow    = (const int*)d_in[1];
    const int*   ecol    = (const int*)d_in[2];
    const float* pre_w   = (const float*)d_in[3];
    const float* lin_w   = (const float*)d_in[4];
    const float* bias    = (const float*)d_in[5];
    const float* avg_log = (const float*)d_in[6];

    const int N = in_sizes[0] / D;
    const int E = in_sizes[1];
    float* out = (float*)d_out;

    permute_w_kernel<<<112, 256>>>(pre_w, lin_w);
    zero_cnt_kernel<<<(N + 255) / 256, 256>>>(N);
    count_kernel<<<(E + 255) / 256, 256>>>(erow, E);
    int nsb = (N + SCAN_BLK - 1) / SCAN_BLK;
    scan_block_kernel<<<nsb, SCAN_BLK>>>(N);
    scan_top_kernel<<<1, 128>>>(nsb);
    scan_add_kernel<<<(N + 256) / 256, 256>>>(N, E);
    scatter_kernel<<<(E + 255) / 256, 256>>>(erow, ecol, E);

    {
        long long threads = (long long)N * 16;
        int blocks = (int)((threads + 255) / 256);
        aggregate_kernel<<<blocks, 256>>>(x, N);
    }

    {
        cudaFuncSetAttribute(finalize_kernel,
                             cudaFuncAttributeMaxDynamicSharedMemorySize,
                             64 * 448 * 4);
        int blocks = (N + 63) / 64;
        finalize_kernel<<<blocks, 256, 64 * 448 * 4>>>(
            x, bias, avg_log, out, N);
    }
}